// round 1
// baseline (speedup 1.0000x reference)
#include <cuda_runtime.h>
#include <stdint.h>

typedef unsigned long long u64;
typedef unsigned int u32;

#define NLEV 5
#define CLSN 16
#define TOPK 1000
#define NTOT 785664
#define KTOT (NLEV * TOPK)     /* 5000 */
#define ROWS (KTOT * CLSN)     /* 80000 */
#define WCAP 2048
#define MAXD 4.135166556742356f

__device__ __constant__ int d_off[6] = {0, 589824, 737280, 774144, 783360, 785664};
__device__ __constant__ int d_len[5] = {589824, 147456, 36864, 9216, 2304};

struct Ptrs {
    const float* anc[NLEV];
    const float* cls[NLEV];
    const float* reg[NLEV];
};

// ---------------- scratch (static device globals; no allocation) ----------------
__device__ u32 g_ord[NTOT];
__device__ u64 g_candA[NTOT];
__device__ u64 g_candB[NTOT];
__device__ u64 g_win[NLEV][WCAP];
__device__ int g_hist[NLEV][4][256];
__device__ int g_ncA[NLEV], g_ncB[NLEV], g_nwin[NLEV], g_krem[NLEV];
__device__ int g_thr[NLEV][4];
__device__ u32 g_sel[KTOT];

// ---------------- K0: reset per-run state ----------------
__global__ void k_reset() {
    int t = threadIdx.x;
    int* hb = &g_hist[0][0][0];
    for (int i = t; i < NLEV * 4 * 256; i += blockDim.x) hb[i] = 0;
    if (t < NLEV) {
        g_ncA[t] = 0;
        g_ncB[t] = 0;
        g_nwin[t] = 0;
        g_krem[t] = TOPK;
    }
}

// ---------------- K1: ruler = max over 16 logits, ordered key, byte-3 histogram --
__global__ void k_ruler(Ptrs p) {
    int g = blockIdx.x * 256 + threadIdx.x;   // grid exactly covers NTOT
    __shared__ int sh[256];
    sh[threadIdx.x] = 0;
    __syncthreads();

    int l = 0;
#pragma unroll
    for (int j = 1; j < NLEV; j++) l += (g >= d_off[j]);
    int i = g - d_off[l];

    const float4* c4 = (const float4*)(p.cls[l]) + (size_t)i * 4;
    float4 a = c4[0], b = c4[1], c = c4[2], d = c4[3];
    float m = fmaxf(fmaxf(fmaxf(a.x, a.y), fmaxf(a.z, a.w)),
                    fmaxf(fmaxf(b.x, b.y), fmaxf(b.z, b.w)));
    m = fmaxf(m, fmaxf(fmaxf(c.x, c.y), fmaxf(c.z, c.w)));
    m = fmaxf(m, fmaxf(fmaxf(d.x, d.y), fmaxf(d.z, d.w)));

    u32 u = __float_as_uint(m);
    u32 ord = (u & 0x80000000u) ? ~u : (u | 0x80000000u);  // monotonic: bigger float -> bigger ord
    g_ord[g] = ord;

    atomicAdd(&sh[ord >> 24], 1);
    __syncthreads();
    // each block lies fully inside one level (all level offsets are multiples of 256)
    if (sh[threadIdx.x]) atomicAdd(&g_hist[l][0][threadIdx.x], sh[threadIdx.x]);
}

// ---------------- resolve pass: find threshold byte, update k_rem ----------------
__global__ void k_resolve(int pass) {
    if (threadIdx.x != 0) return;
    int l = blockIdx.x;
    int krem = g_krem[l];
    const int* h = g_hist[l][pass];
    int cum = 0, b = 255;
    for (; b > 0; b--) {
        int c = h[b];
        if (cum + c >= krem) break;
        cum += c;
    }
    g_thr[l][pass] = b;
    g_krem[l] = krem - cum;
    if (pass == 2) g_ncA[l] = 0;  // candA is consumed by P2; reused as P3 output
}

// ---------------- P1: full scan of ord keys, byte 3 ----------------
__global__ void k_part1() {
    int g = blockIdx.x * 256 + threadIdx.x;
    int l = 0;
#pragma unroll
    for (int j = 1; j < NLEV; j++) l += (g >= d_off[j]);
    u32 ord = g_ord[g];
    int byte = (int)(ord >> 24);
    int thr = g_thr[l][0];
    if (byte > thr) {
        int w = atomicAdd(&g_nwin[l], 1);
        if (w < WCAP) g_win[l][w] = ((u64)ord << 32) | (u32)(g - d_off[l]);
    } else if (byte == thr) {
        int c = atomicAdd(&g_ncA[l], 1);
        g_candA[d_off[l] + c] = ((u64)ord << 32) | (u32)(g - d_off[l]);
        atomicAdd(&g_hist[l][1][(ord >> 16) & 0xFFu], 1);
    }
}

// ---------------- P2: candA -> candB on byte 2 ----------------
__global__ void k_part2() {
    int l = blockIdx.y;
    int n = g_ncA[l];
    int thr = g_thr[l][1];
    for (int i = blockIdx.x * blockDim.x + threadIdx.x; i < n; i += gridDim.x * blockDim.x) {
        u64 key = g_candA[d_off[l] + i];
        u32 ord = (u32)(key >> 32);
        int byte = (int)((ord >> 16) & 0xFFu);
        if (byte > thr) {
            int w = atomicAdd(&g_nwin[l], 1);
            if (w < WCAP) g_win[l][w] = key;
        } else if (byte == thr) {
            int c = atomicAdd(&g_ncB[l], 1);
            g_candB[d_off[l] + c] = key;
            atomicAdd(&g_hist[l][2][(ord >> 8) & 0xFFu], 1);
        }
    }
}

// ---------------- P3: candB -> candA on byte 1 ----------------
__global__ void k_part3() {
    int l = blockIdx.y;
    int n = g_ncB[l];
    int thr = g_thr[l][2];
    for (int i = blockIdx.x * blockDim.x + threadIdx.x; i < n; i += gridDim.x * blockDim.x) {
        u64 key = g_candB[d_off[l] + i];
        u32 ord = (u32)(key >> 32);
        int byte = (int)((ord >> 8) & 0xFFu);
        if (byte > thr) {
            int w = atomicAdd(&g_nwin[l], 1);
            if (w < WCAP) g_win[l][w] = key;
        } else if (byte == thr) {
            int c = atomicAdd(&g_ncA[l], 1);
            g_candA[d_off[l] + c] = key;
            atomicAdd(&g_hist[l][3][ord & 0xFFu], 1);
        }
    }
}

// ---------------- P4: byte 0; equal-key elements all become winners --------------
// (sort + take-first-1000 resolves the index tie-break exactly like jax top_k)
__global__ void k_part4() {
    int l = blockIdx.y;
    int n = g_ncA[l];
    int thr = g_thr[l][3];
    for (int i = blockIdx.x * blockDim.x + threadIdx.x; i < n; i += gridDim.x * blockDim.x) {
        u64 key = g_candA[d_off[l] + i];
        int byte = (int)((u32)(key >> 32) & 0xFFu);
        if (byte >= thr) {
            int w = atomicAdd(&g_nwin[l], 1);
            if (w < WCAP) g_win[l][w] = key;
        }
    }
}

// ---------------- sort winners: ascending on (~ord, idx) == (value desc, idx asc) -
__global__ void k_sort() {
    __shared__ u64 s[WCAP];
    int l = blockIdx.x;
    int n = g_nwin[l];
    if (n > WCAP) n = WCAP;
    int t = threadIdx.x;
    for (int i = t; i < WCAP; i += 1024)
        s[i] = (i < n) ? (g_win[l][i] ^ 0xFFFFFFFF00000000ULL) : 0xFFFFFFFFFFFFFFFFULL;
    __syncthreads();
    for (int k = 2; k <= WCAP; k <<= 1) {
        for (int j = k >> 1; j > 0; j >>= 1) {
            for (int i = t; i < WCAP; i += 1024) {
                int pr = i ^ j;
                if (pr > i) {
                    bool up = ((i & k) == 0);
                    u64 x = s[i], y = s[pr];
                    if ((x > y) == up) { s[i] = y; s[pr] = x; }
                }
            }
            __syncthreads();
        }
    }
    if (t < TOPK) g_sel[l * TOPK + t] = (u32)(s[t] & 0xFFFFFFFFu);
}

// ---------------- final: gather, sigmoid, decode, tile x16 classes ---------------
__global__ void k_final(Ptrs p, float* __restrict__ out) {
    int r = blockIdx.x * 256 + threadIdx.x;
    if (r >= ROWS) return;
    int k = r >> 4;
    int c = r & 15;
    int l = k / TOPK;
    u32 idx = g_sel[k];
    if (idx >= (u32)d_len[l]) idx = 0;  // safety (never hit on valid data)

    float4 a4 = ((const float4*)p.anc[l])[idx];
    float4 r4 = ((const float4*)p.reg[l])[idx * 2];   // first 4 of the 8 reg values
    float score = p.cls[l][(size_t)idx * 16 + c];

    float w = a4.z - a4.x, h = a4.w - a4.y;
    float cx = a4.x + 0.5f * w, cy = a4.y + 0.5f * h;
    float pcx = cx + r4.x * w, pcy = cy + r4.y * h;
    float pw = w * expf(fminf(r4.z, MAXD));
    float ph = h * expf(fminf(r4.w, MAXD));
    float sg = 1.0f / (1.0f + expf(-score));

    float* o = out + (size_t)r * 6;
    o[0] = pcx - 0.5f * pw;
    o[1] = pcy - 0.5f * ph;
    o[2] = pcx + 0.5f * pw;
    o[3] = pcy + 0.5f * ph;
    o[4] = sg;
    o[5] = (float)(c + 1);
}

extern "C" void kernel_launch(void* const* d_in, const int* in_sizes, int n_in,
                              void* d_out, int out_size) {
    (void)in_sizes; (void)n_in; (void)out_size;
    Ptrs p;
    for (int l = 0; l < NLEV; l++) {
        p.anc[l] = (const float*)d_in[3 * l + 0];
        p.cls[l] = (const float*)d_in[3 * l + 1];
        p.reg[l] = (const float*)d_in[3 * l + 2];
    }

    k_reset<<<1, 1024>>>();
    k_ruler<<<NTOT / 256, 256>>>(p);
    k_resolve<<<NLEV, 32>>>(0);
    k_part1<<<NTOT / 256, 256>>>();
    k_resolve<<<NLEV, 32>>>(1);
    dim3 gmid(32, NLEV);
    k_part2<<<gmid, 256>>>();
    k_resolve<<<NLEV, 32>>>(2);
    k_part3<<<gmid, 256>>>();
    k_resolve<<<NLEV, 32>>>(3);
    k_part4<<<gmid, 256>>>();
    k_sort<<<NLEV, 1024>>>();
    k_final<<<(ROWS + 255) / 256, 256>>>(p, (float*)d_out);
}